// round 6
// baseline (speedup 1.0000x reference)
#include <cuda_runtime.h>
#include <cuda_bf16.h>

// Problem constants (fixed by reference setup_inputs)
#define BATCH 4096
#define CELL  400
#define CELL4 100     // CELL/4
#define KMIX  10
#define NP    30      // 3*KMIX params
#define TLEN  256
#define VDIM  80
#define RPB   8       // batch rows per block in kernel A
#define NTA   256
#define NTB   320

// phi scratch: [BATCH, TLEN] fp32 = 4 MB (device global, allocation-free)
__device__ float g_phi[(size_t)BATCH * TLEN];

// Kernel A dynamic shared layout (floats):
//   sW [NP*CELL]=12000, sx [RPB*CELL]=3200, sp [RPB*NP]=240,
//   sal/sbe/ska [RPB*KMIX]=80 each, sbias [32]
#define SMEM_A_FLOATS (12000 + 3200 + 240 + 3*80 + 32)
#define SMEM_A_BYTES  (SMEM_A_FLOATS * 4)

__global__ __launch_bounds__(NTA)
void params_phi_kernel(const float* __restrict__ x,
                       const float* __restrict__ kappa_old,
                       const float* __restrict__ W,
                       const float* __restrict__ bias,
                       float* __restrict__ out_kappa)
{
    extern __shared__ float smem[];
    float* sW    = smem;              // 12000
    float* sx    = sW + 12000;        // 3200
    float* sp    = sx + 3200;         // 240  [RPB][NP]
    float* sal   = sp + 240;          // 80   [RPB][KMIX]
    float* sbe   = sal + 80;
    float* ska   = sbe + 80;
    float* sbias = ska + 80;

    const int tid = threadIdx.x;
    const int b0  = blockIdx.x * RPB;

    // ---- stage W + x rows + bias (all float4) ----
    const float4* W4 = (const float4*)W;
    for (int i = tid; i < 12000 / 4; i += NTA) ((float4*)sW)[i] = W4[i];
    const float4* x4g = (const float4*)(x + (size_t)b0 * CELL);
    for (int i = tid; i < RPB * CELL4; i += NTA) ((float4*)sx)[i] = x4g[i];
    if (tid < NP) sbias[tid] = bias[tid];
    __syncthreads();

    // ---- mat-vec: warp w handles row w (8 warps, 8 rows), acc[30] ----
    const int warp = tid >> 5;
    const int lane = tid & 31;
    {
        const float4* sx4 = (const float4*)(sx + warp * CELL);
        const float4* sW4 = (const float4*)sW;
        float acc[NP];
        #pragma unroll
        for (int p = 0; p < NP; p++) acc[p] = 0.0f;

        for (int c4 = lane; c4 < CELL4; c4 += 32) {
            const float4 xv = sx4[c4];
            #pragma unroll
            for (int p = 0; p < NP; p++) {
                const float4 wv = sW4[p * CELL4 + c4];
                acc[p] += xv.x * wv.x + xv.y * wv.y + xv.z * wv.z + xv.w * wv.w;
            }
        }
        #pragma unroll
        for (int p = 0; p < NP; p++) {
            float s = acc[p];
            #pragma unroll
            for (int off = 16; off > 0; off >>= 1)
                s += __shfl_xor_sync(0xffffffffu, s, off);
            if (lane == 0) sp[warp * NP + p] = s + sbias[p];
        }
    }
    __syncthreads();

    // ---- alpha/beta/kappa transforms (80 threads); write kappa ----
    if (tid < RPB * KMIX) {
        const int r = tid / KMIX, k = tid - r * KMIX;
        const float* prow = sp + r * NP;
        const float kap = kappa_old[(size_t)(b0 + r) * KMIX + k] + __expf(prow[2 * KMIX + k]);
        sal[r * KMIX + k] = __expf(prow[k]);
        sbe[r * KMIX + k] = __expf(prow[KMIX + k]);
        ska[r * KMIX + k] = kap;
        out_kappa[(size_t)(b0 + r) * KMIX + k] = kap;
    }
    __syncthreads();

    // ---- phi: 8 rows x 256 t; thread tid = t ----
    const float u = (float)tid;   // NTA == TLEN
    #pragma unroll
    for (int r = 0; r < RPB; r++) {
        float s = 0.0f;
        #pragma unroll
        for (int k = 0; k < KMIX; k++) {
            const float d = ska[r * KMIX + k] - u;
            s += sal[r * KMIX + k] * __expf(-sbe[r * KMIX + k] * d * d);
        }
        g_phi[(size_t)(b0 + r) * TLEN + tid] = s;
    }
}

// ---- Kernel B: pure streaming einsum, float4 (UNCHANGED: 51.1us @ 85.0% DRAM) ----
__global__ __launch_bounds__(NTB)
void stream_kernel(const float* __restrict__ onehots,
                   float* __restrict__ out_weight)
{
    const int b   = blockIdx.x;
    const int tid = threadIdx.x;

    __shared__ float  sphi[TLEN];
    __shared__ float4 wpart[16 * 20];   // [t0][c]

    if (tid < TLEN) sphi[tid] = g_phi[(size_t)b * TLEN + tid];
    __syncthreads();

    const float4* oh = (const float4*)(onehots + (size_t)b * TLEN * VDIM);
    const int c  = tid % 20;    // float4 column (v/4)
    const int t0 = tid / 20;    // 0..15

    float4 acc = make_float4(0.f, 0.f, 0.f, 0.f);
    #pragma unroll
    for (int j = 0; j < 16; j++) {
        const int t = t0 + j * 16;
        const float  p = sphi[t];
        const float4 o = oh[t * 20 + c];
        acc.x += p * o.x; acc.y += p * o.y; acc.z += p * o.z; acc.w += p * o.w;
    }
    wpart[t0 * 20 + c] = acc;
    __syncthreads();

    if (tid < VDIM) {
        const float* wp = (const float*)wpart;
        float s = 0.0f;
        #pragma unroll
        for (int j = 0; j < 16; j++) s += wp[j * VDIM + tid];
        out_weight[(size_t)b * VDIM + tid] = s;
    }
}

extern "C" void kernel_launch(void* const* d_in, const int* in_sizes, int n_in,
                              void* d_out, int out_size)
{
    const float* x         = (const float*)d_in[0];   // [B, CELL]
    const float* kappa_old = (const float*)d_in[1];   // [B, K]
    const float* onehots   = (const float*)d_in[2];   // [B, T, V]
    const float* W         = (const float*)d_in[3];   // [3K, CELL]
    const float* bias      = (const float*)d_in[4];   // [3K]

    float* out_weight = (float*)d_out;                        // [B, V]
    float* out_kappa  = (float*)d_out + (size_t)BATCH * VDIM; // [B, K]

    cudaFuncSetAttribute(params_phi_kernel,
                         cudaFuncAttributeMaxDynamicSharedMemorySize, SMEM_A_BYTES);

    params_phi_kernel<<<BATCH / RPB, NTA, SMEM_A_BYTES>>>(x, kappa_old, W, bias, out_kappa);
    stream_kernel<<<BATCH, NTB>>>(onehots, out_weight);
}

// round 7
// speedup vs baseline: 1.0823x; 1.0823x over previous
#include <cuda_runtime.h>
#include <cuda_bf16.h>

// Problem constants (fixed by reference setup_inputs)
#define BATCH 4096
#define CELL  400
#define CELL4 100    // CELL/4
#define KMIX  10
#define NP    30     // 3*KMIX params
#define TLEN  256
#define VDIM  80
#define RPA   8      // rows per block, kernel A  (warp = row)
#define NTA   256
#define NTB   320

// alpha/beta/kappa scratch: [BATCH][30] = [alpha(10)|beta(10)|kappa(10)] per row
__device__ float g_abk[(size_t)BATCH * NP];

// Kernel A smem (floats): sW padded [32][401] = 12832, sx [RPA][400] = 3200, sbias 32
#define SW_STRIDE 401
#define SMEM_A_FLOATS (32 * SW_STRIDE + RPA * CELL + 32)
#define SMEM_A_BYTES  (SMEM_A_FLOATS * 4)

__global__ __launch_bounds__(NTA)
void params_kernel(const float* __restrict__ x,
                   const float* __restrict__ kappa_old,
                   const float* __restrict__ W,
                   const float* __restrict__ bias,
                   float* __restrict__ out_kappa)
{
    extern __shared__ float smem[];
    float* sW    = smem;                    // [32][401] (rows 30,31 garbage-pad)
    float* sx    = sW + 32 * SW_STRIDE;     // [RPA][400]
    float* sbias = sx + RPA * CELL;         // 32

    const int tid = threadIdx.x;
    const int b0  = blockIdx.x * RPA;

    // ---- stage W into padded smem (stride 401 -> conflict-free lane-distinct reads)
    {
        const float4* W4 = (const float4*)W;
        for (int i4 = tid; i4 < NP * CELL4; i4 += NTA) {
            const int p  = i4 / CELL4;
            const int c4 = i4 - p * CELL4;
            const float4 v = W4[i4];
            float* dst = sW + p * SW_STRIDE + c4 * 4;
            dst[0] = v.x; dst[1] = v.y; dst[2] = v.z; dst[3] = v.w;
        }
    }
    // ---- stage 8 x-rows (contiguous float4)
    {
        const float4* x4g = (const float4*)(x + (size_t)b0 * CELL);
        for (int i = tid; i < RPA * CELL4; i += NTA) ((float4*)sx)[i] = x4g[i];
    }
    if (tid < NP) sbias[tid] = bias[tid];
    __syncthreads();

    // ---- mat-vec: warp = row, lane = param (lanes 30,31 compute garbage, unused)
    const int warp = tid >> 5;
    const int lane = tid & 31;
    const float4* xr = (const float4*)(sx + warp * CELL);
    const float*  wr = sW + lane * SW_STRIDE;

    float acc = 0.0f;
    #pragma unroll 5
    for (int c4 = 0; c4 < CELL4; c4++) {
        const float4 xv = xr[c4];            // broadcast LDS.128
        const float* w4 = wr + c4 * 4;       // lane-distinct, stride-401 banks
        acc += xv.x * w4[0] + xv.y * w4[1] + xv.z * w4[2] + xv.w * w4[3];
    }
    float v = acc + ((lane < NP) ? sbias[lane] : 0.0f);

    // lane k needs params k (alpha), k+10 (beta), k+20 (kappa-delta)
    const unsigned full = 0xffffffffu;
    const float v10 = __shfl_sync(full, v, (lane + 10) & 31);
    const float v20 = __shfl_sync(full, v, (lane + 20) & 31);

    if (lane < KMIX) {
        const int row = b0 + warp;
        const float alpha = __expf(v);
        const float beta  = __expf(v10);
        const float kap   = kappa_old[(size_t)row * KMIX + lane] + __expf(v20);
        float* dst = g_abk + (size_t)row * NP;
        dst[lane]            = alpha;
        dst[KMIX + lane]     = beta;
        dst[2 * KMIX + lane] = kap;
        out_kappa[(size_t)row * KMIX + lane] = kap;
    }
}

// ---- Kernel B: phi prologue (tiny) + streaming einsum body (proven 51us @85% DRAM)
__global__ __launch_bounds__(NTB)
void stream_kernel(const float* __restrict__ onehots,
                   float* __restrict__ out_weight)
{
    const int b   = blockIdx.x;
    const int tid = threadIdx.x;

    __shared__ float  sabk[32];
    __shared__ float  sphi[TLEN];
    __shared__ float4 wpart[16 * 20];   // [t0][c]

    if (tid < NP) sabk[tid] = g_abk[(size_t)b * NP + tid];
    __syncthreads();

    if (tid < TLEN) {
        const float u = (float)tid;
        float s = 0.0f;
        #pragma unroll
        for (int k = 0; k < KMIX; k++) {
            const float d = sabk[2 * KMIX + k] - u;
            s += sabk[k] * __expf(-sabk[KMIX + k] * d * d);
        }
        sphi[tid] = s;
    }
    __syncthreads();

    const float4* oh = (const float4*)(onehots + (size_t)b * TLEN * VDIM);
    const int c  = tid % 20;    // float4 column (v/4)
    const int t0 = tid / 20;    // 0..15

    float4 acc = make_float4(0.f, 0.f, 0.f, 0.f);
    #pragma unroll
    for (int j = 0; j < 16; j++) {
        const int t = t0 + j * 16;
        const float  p = sphi[t];
        const float4 o = oh[t * 20 + c];
        acc.x += p * o.x; acc.y += p * o.y; acc.z += p * o.z; acc.w += p * o.w;
    }
    wpart[t0 * 20 + c] = acc;
    __syncthreads();

    if (tid < VDIM) {
        const float* wp = (const float*)wpart;
        float s = 0.0f;
        #pragma unroll
        for (int j = 0; j < 16; j++) s += wp[j * VDIM + tid];
        out_weight[(size_t)b * VDIM + tid] = s;
    }
}

extern "C" void kernel_launch(void* const* d_in, const int* in_sizes, int n_in,
                              void* d_out, int out_size)
{
    const float* x         = (const float*)d_in[0];   // [B, CELL]
    const float* kappa_old = (const float*)d_in[1];   // [B, K]
    const float* onehots   = (const float*)d_in[2];   // [B, T, V]
    const float* W         = (const float*)d_in[3];   // [3K, CELL]
    const float* bias      = (const float*)d_in[4];   // [3K]

    float* out_weight = (float*)d_out;                        // [B, V]
    float* out_kappa  = (float*)d_out + (size_t)BATCH * VDIM; // [B, K]

    cudaFuncSetAttribute(params_kernel,
                         cudaFuncAttributeMaxDynamicSharedMemorySize, SMEM_A_BYTES);

    params_kernel<<<BATCH / RPA, NTA, SMEM_A_BYTES>>>(x, kappa_old, W, bias, out_kappa);
    stream_kernel<<<BATCH, NTB>>>(onehots, out_weight);
}

// round 8
// speedup vs baseline: 1.2772x; 1.1801x over previous
#include <cuda_runtime.h>
#include <cuda_bf16.h>

// Problem constants (fixed by reference setup_inputs)
#define BATCH 4096
#define CELL  400
#define CELL4 100    // CELL/4
#define KMIX  10
#define NP    30     // 3*KMIX
#define TLEN  256
#define VDIM  80
#define NT    320    // 10 warps

__global__ __launch_bounds__(NT)
void window_fused(const float* __restrict__ x,
                  const float* __restrict__ kappa_old,
                  const float* __restrict__ onehots,
                  const float* __restrict__ W,
                  const float* __restrict__ bias,
                  float* __restrict__ out_weight,   // [B, V]
                  float* __restrict__ out_kappa)    // [B, K]
{
    const int b   = blockIdx.x;
    const int tid = threadIdx.x;
    const int warp = tid >> 5;
    const int lane = tid & 31;

    __shared__ float  sx[CELL];
    __shared__ float  sparams[32];
    __shared__ float  sal[16], sbe[16], ska[16];
    __shared__ float  sphi[TLEN];
    __shared__ float4 wpart[16 * 20];

    // ---- stage x[b] (float4, coalesced) ----
    {
        const float4* x4 = (const float4*)(x + (size_t)b * CELL);
        for (int i = tid; i < CELL4; i += NT) ((float4*)sx)[i] = x4[i];
    }
    __syncthreads();

    // ---- mat-vec: warp w computes params {w, w+10, w+20} ----
    // W rows read as coalesced LDG.128 (hot in L2 after first wave)
    {
        const float4* W4  = (const float4*)W;
        const float4* sx4 = (const float4*)sx;
        float s0 = 0.f, s1 = 0.f, s2 = 0.f;
        for (int c4 = lane; c4 < CELL4; c4 += 32) {
            const float4 xv = sx4[c4];
            const float4 w0 = W4[(warp)      * CELL4 + c4];
            const float4 w1 = W4[(warp + 10) * CELL4 + c4];
            const float4 w2 = W4[(warp + 20) * CELL4 + c4];
            s0 += xv.x * w0.x + xv.y * w0.y + xv.z * w0.z + xv.w * w0.w;
            s1 += xv.x * w1.x + xv.y * w1.y + xv.z * w1.z + xv.w * w1.w;
            s2 += xv.x * w2.x + xv.y * w2.y + xv.z * w2.z + xv.w * w2.w;
        }
        #pragma unroll
        for (int off = 16; off > 0; off >>= 1) {
            s0 += __shfl_xor_sync(0xffffffffu, s0, off);
            s1 += __shfl_xor_sync(0xffffffffu, s1, off);
            s2 += __shfl_xor_sync(0xffffffffu, s2, off);
        }
        if (lane == 0) {
            sparams[warp]      = s0 + bias[warp];
            sparams[warp + 10] = s1 + bias[warp + 10];
            sparams[warp + 20] = s2 + bias[warp + 20];
        }
    }
    __syncthreads();

    // ---- transforms (__expf: MUFU-based, plenty accurate vs 1e-3) ----
    if (tid < KMIX) {
        const float kap = kappa_old[(size_t)b * KMIX + tid] + __expf(sparams[2 * KMIX + tid]);
        sal[tid] = __expf(sparams[tid]);
        sbe[tid] = __expf(sparams[KMIX + tid]);
        ska[tid] = kap;
        out_kappa[(size_t)b * KMIX + tid] = kap;
    }
    __syncthreads();

    // ---- phi[t] ----
    if (tid < TLEN) {
        const float u = (float)tid;
        float s = 0.0f;
        #pragma unroll
        for (int k = 0; k < KMIX; k++) {
            const float d = ska[k] - u;
            s += sal[k] * __expf(-sbe[k] * d * d);
        }
        sphi[tid] = s;
    }
    __syncthreads();

    // ---- streaming einsum body (proven shape: float4, coalesced) ----
    const float4* oh = (const float4*)(onehots + (size_t)b * TLEN * VDIM);
    const int c  = tid % 20;    // float4 column (v/4)
    const int t0 = tid / 20;    // 0..15

    float4 acc = make_float4(0.f, 0.f, 0.f, 0.f);
    #pragma unroll
    for (int j = 0; j < 16; j++) {
        const int t = t0 + j * 16;
        const float  p = sphi[t];
        const float4 o = oh[t * 20 + c];
        acc.x += p * o.x; acc.y += p * o.y; acc.z += p * o.z; acc.w += p * o.w;
    }
    wpart[t0 * 20 + c] = acc;
    __syncthreads();

    if (tid < VDIM) {
        const float* wp = (const float*)wpart;
        float s = 0.0f;
        #pragma unroll
        for (int j = 0; j < 16; j++) s += wp[j * VDIM + tid];
        out_weight[(size_t)b * VDIM + tid] = s;
    }
}

extern "C" void kernel_launch(void* const* d_in, const int* in_sizes, int n_in,
                              void* d_out, int out_size)
{
    const float* x         = (const float*)d_in[0];   // [B, CELL]
    const float* kappa_old = (const float*)d_in[1];   // [B, K]
    const float* onehots   = (const float*)d_in[2];   // [B, T, V]
    const float* W         = (const float*)d_in[3];   // [3K, CELL]
    const float* bias      = (const float*)d_in[4];   // [3K]

    float* out_weight = (float*)d_out;                        // [B, V]
    float* out_kappa  = (float*)d_out + (size_t)BATCH * VDIM; // [B, K]

    window_fused<<<BATCH, NT>>>(x, kappa_old, onehots, W, bias,
                                out_weight, out_kappa);
}

// round 9
// speedup vs baseline: 1.3363x; 1.0463x over previous
#include <cuda_runtime.h>
#include <cuda_bf16.h>
#include <cstdint>

// Problem constants (fixed by reference setup_inputs)
#define BATCH 4096
#define CELL  400
#define CELL4 100    // CELL/4
#define KMIX  10
#define NP    30     // 3*KMIX
#define TLEN  256
#define VDIM  80
#define NT    320    // 10 warps
#define JPRE  4      // first 4 of 16 t-chunks prefetched to smem (t = 0..63)
#define PRE_F4 (JPRE * 16 * 20)   // 1280 float4s = 20 KB

#define CP_ASYNC_16(smem_u32, gptr) \
    asm volatile("cp.async.cg.shared.global [%0], [%1], 16;" :: "r"(smem_u32), "l"(gptr))
#define CP_ASYNC_COMMIT()   asm volatile("cp.async.commit_group;" ::: "memory")
#define CP_ASYNC_WAIT_ALL() asm volatile("cp.async.wait_group 0;" ::: "memory")

__global__ __launch_bounds__(NT)
void window_fused(const float* __restrict__ x,
                  const float* __restrict__ kappa_old,
                  const float* __restrict__ onehots,
                  const float* __restrict__ W,
                  const float* __restrict__ bias,
                  float* __restrict__ out_weight,   // [B, V]
                  float* __restrict__ out_kappa)    // [B, K]
{
    const int b   = blockIdx.x;
    const int tid = threadIdx.x;
    const int warp = tid >> 5;
    const int lane = tid & 31;

    __shared__ float4 soh[PRE_F4];      // first 64 t-rows of onehots[b]
    __shared__ float  sx[CELL];
    __shared__ float  sparams[32];
    __shared__ float  sal[16], sbe[16], ska[16];
    __shared__ float  sphi[TLEN];
    __shared__ float4 wpart[16 * 20];

    const float4* oh = (const float4*)(onehots + (size_t)b * TLEN * VDIM);

    // ---- issue async prefetch of first 20KB of onehots[b] (fills during prologue)
    {
        uint32_t soh_u32 = (uint32_t)__cvta_generic_to_shared(soh);
        #pragma unroll
        for (int k = 0; k < PRE_F4 / NT; k++) {
            const int i = tid + k * NT;
            CP_ASYNC_16(soh_u32 + i * 16, oh + i);
        }
        CP_ASYNC_COMMIT();
    }

    // ---- stage x[b] (float4, coalesced) ----
    {
        const float4* x4 = (const float4*)(x + (size_t)b * CELL);
        for (int i = tid; i < CELL4; i += NT) ((float4*)sx)[i] = x4[i];
    }
    __syncthreads();

    // ---- mat-vec: warp w computes params {w, w+10, w+20} (W hot in L2) ----
    {
        const float4* W4  = (const float4*)W;
        const float4* sx4 = (const float4*)sx;
        float s0 = 0.f, s1 = 0.f, s2 = 0.f;
        #pragma unroll
        for (int c4 = lane; c4 < CELL4; c4 += 32) {
            const float4 xv = sx4[c4];
            const float4 w0 = W4[(warp)      * CELL4 + c4];
            const float4 w1 = W4[(warp + 10) * CELL4 + c4];
            const float4 w2 = W4[(warp + 20) * CELL4 + c4];
            s0 += xv.x * w0.x + xv.y * w0.y + xv.z * w0.z + xv.w * w0.w;
            s1 += xv.x * w1.x + xv.y * w1.y + xv.z * w1.z + xv.w * w1.w;
            s2 += xv.x * w2.x + xv.y * w2.y + xv.z * w2.z + xv.w * w2.w;
        }
        #pragma unroll
        for (int off = 16; off > 0; off >>= 1) {
            s0 += __shfl_xor_sync(0xffffffffu, s0, off);
            s1 += __shfl_xor_sync(0xffffffffu, s1, off);
            s2 += __shfl_xor_sync(0xffffffffu, s2, off);
        }
        if (lane == 0) {
            sparams[warp]      = s0 + bias[warp];
            sparams[warp + 10] = s1 + bias[warp + 10];
            sparams[warp + 20] = s2 + bias[warp + 20];
        }
    }
    __syncthreads();

    // ---- transforms ----
    if (tid < KMIX) {
        const float kap = kappa_old[(size_t)b * KMIX + tid] + __expf(sparams[2 * KMIX + tid]);
        sal[tid] = __expf(sparams[tid]);
        sbe[tid] = __expf(sparams[KMIX + tid]);
        ska[tid] = kap;
        out_kappa[(size_t)b * KMIX + tid] = kap;
    }
    __syncthreads();

    // ---- phi[t] ----
    if (tid < TLEN) {
        const float u = (float)tid;
        float s = 0.0f;
        #pragma unroll
        for (int k = 0; k < KMIX; k++) {
            const float d = ska[k] - u;
            s += sal[k] * __expf(-sbe[k] * d * d);
        }
        sphi[tid] = s;
    }
    CP_ASYNC_WAIT_ALL();
    __syncthreads();

    // ---- streaming einsum: j<JPRE from smem, rest from global ----
    const int c  = tid % 20;    // float4 column (v/4)
    const int t0 = tid / 20;    // 0..15

    float4 acc = make_float4(0.f, 0.f, 0.f, 0.f);
    #pragma unroll
    for (int j = 0; j < JPRE; j++) {
        const int t = t0 + j * 16;
        const float  p = sphi[t];
        const float4 o = soh[t * 20 + c];
        acc.x += p * o.x; acc.y += p * o.y; acc.z += p * o.z; acc.w += p * o.w;
    }
    #pragma unroll
    for (int j = JPRE; j < 16; j++) {
        const int t = t0 + j * 16;
        const float  p = sphi[t];
        const float4 o = oh[t * 20 + c];
        acc.x += p * o.x; acc.y += p * o.y; acc.z += p * o.z; acc.w += p * o.w;
    }
    wpart[t0 * 20 + c] = acc;
    __syncthreads();

    if (tid < VDIM) {
        const float* wp = (const float*)wpart;
        float s = 0.0f;
        #pragma unroll
        for (int j = 0; j < 16; j++) s += wp[j * VDIM + tid];
        out_weight[(size_t)b * VDIM + tid] = s;
    }
}

extern "C" void kernel_launch(void* const* d_in, const int* in_sizes, int n_in,
                              void* d_out, int out_size)
{
    const float* x         = (const float*)d_in[0];   // [B, CELL]
    const float* kappa_old = (const float*)d_in[1];   // [B, K]
    const float* onehots   = (const float*)d_in[2];   // [B, T, V]
    const float* W         = (const float*)d_in[3];   // [3K, CELL]
    const float* bias      = (const float*)d_in[4];   // [3K]

    float* out_weight = (float*)d_out;                        // [B, V]
    float* out_kappa  = (float*)d_out + (size_t)BATCH * VDIM; // [B, K]

    window_fused<<<BATCH, NT>>>(x, kappa_old, onehots, W, bias,
                                out_weight, out_kappa);
}